// round 2
// baseline (speedup 1.0000x reference)
#include <cuda_runtime.h>
#include <math.h>

#define B_SZ    4
#define LSEQ    2048
#define D_MODEL 1024
#define D_INNER 2048
#define D_HALF  1024
#define D_STATE 16
#define DT_RANK 64
#define ROWS    (B_SZ * LSEQ)   /* 8192 */
#define XDBL_W  96              /* DT_RANK + 2*D_STATE */

/* ------------------------------------------------------------------ */
/* Scratch (allocation-free rule: __device__ globals)                  */
/* ------------------------------------------------------------------ */
__device__ float g_xz   [ROWS * D_INNER];   /* 64 MB */
__device__ float g_u    [ROWS * D_HALF];    /* 32 MB  xs after conv+silu */
__device__ float g_xdbl [ROWS * XDBL_W];    /*  3 MB  [dt_low | B | C]   */
__device__ float g_delta[ROWS * D_HALF];    /* 32 MB */
__device__ float g_cat  [ROWS * D_INNER];   /* 64 MB  [y | z]            */

/* ------------------------------------------------------------------ */
/* Generic fp32 SGEMM: C = A(MxK) @ B(KxN), row-major, strided.        */
/* mode 0: plain; mode 1: softplus(v + 2*bias[col]); mode 2: v+bias.   */
/* Requirements: M % 128 == 0, K % 16 == 0, lda/ldb % 4 == 0, N % 4==0 */
/* ------------------------------------------------------------------ */
__global__ __launch_bounds__(256)
void sgemm_kernel(const float* __restrict__ A, const float* __restrict__ B,
                  float* __restrict__ C, int M, int N, int K,
                  int lda, int ldb, int ldc,
                  int mode, const float* __restrict__ bias)
{
    const int BM = 128, BN = 128, BK = 16;
    __shared__ float As[BK][BM];
    __shared__ float Bs[BK][BN];

    const int block_row = blockIdx.y * BM;
    const int block_col = blockIdx.x * BN;
    const int tid = threadIdx.x;
    const int tr  = tid >> 4;          /* 0..15 */
    const int tc  = tid & 15;          /* 0..15 */

    float acc[8][8];
#pragma unroll
    for (int i = 0; i < 8; i++)
#pragma unroll
        for (int j = 0; j < 8; j++) acc[i][j] = 0.f;

    const int a_row = tid >> 2;          /* 0..63  */
    const int a_col = (tid & 3) << 2;    /* 0,4,8,12 */
    const int b_row = tid >> 5;          /* 0..7   */
    const int b_col = (tid & 31) << 2;   /* 0..124 */

    for (int k0 = 0; k0 < K; k0 += BK) {
#pragma unroll
        for (int i = 0; i < 2; i++) {
            int r = a_row + i * 64;
            float4 v = *reinterpret_cast<const float4*>(
                &A[(size_t)(block_row + r) * lda + k0 + a_col]);
            As[a_col + 0][r] = v.x; As[a_col + 1][r] = v.y;
            As[a_col + 2][r] = v.z; As[a_col + 3][r] = v.w;
        }
#pragma unroll
        for (int i = 0; i < 2; i++) {
            int r = b_row + i * 8;
            int col = block_col + b_col;
            float4 v = make_float4(0.f, 0.f, 0.f, 0.f);
            if (col < N)
                v = *reinterpret_cast<const float4*>(&B[(size_t)(k0 + r) * ldb + col]);
            *reinterpret_cast<float4*>(&Bs[r][b_col]) = v;
        }
        __syncthreads();

#pragma unroll
        for (int kk = 0; kk < BK; kk++) {
            float4 a0 = *reinterpret_cast<const float4*>(&As[kk][tr * 8]);
            float4 a1 = *reinterpret_cast<const float4*>(&As[kk][tr * 8 + 4]);
            float4 b0 = *reinterpret_cast<const float4*>(&Bs[kk][tc * 8]);
            float4 b1 = *reinterpret_cast<const float4*>(&Bs[kk][tc * 8 + 4]);
            float ar[8] = {a0.x, a0.y, a0.z, a0.w, a1.x, a1.y, a1.z, a1.w};
            float br[8] = {b0.x, b0.y, b0.z, b0.w, b1.x, b1.y, b1.z, b1.w};
#pragma unroll
            for (int i = 0; i < 8; i++)
#pragma unroll
                for (int j = 0; j < 8; j++)
                    acc[i][j] = fmaf(ar[i], br[j], acc[i][j]);
        }
        __syncthreads();
    }

#pragma unroll
    for (int i = 0; i < 8; i++) {
        int row = block_row + tr * 8 + i;
#pragma unroll
        for (int j = 0; j < 8; j++) {
            int col = block_col + tc * 8 + j;
            if (col < N) {
                float v = acc[i][j];
                if (mode == 1) {
                    v += 2.f * bias[col];
                    v = (v > 20.f) ? v : log1pf(__expf(v));
                } else if (mode == 2) {
                    v += bias[col];
                }
                C[(size_t)row * ldc + col] = v;
            }
        }
    }
}

/* ------------------------------------------------------------------ */
/* Depthwise conv1d (k=4, SAME: pad_lo=1, pad_hi=2) + SiLU on both     */
/* halves of xz. xs -> g_u, z -> right half of g_cat.                  */
/* ------------------------------------------------------------------ */
__global__ __launch_bounds__(256)
void conv_silu_kernel(const float* __restrict__ wx, const float* __restrict__ bx,
                      const float* __restrict__ wz, const float* __restrict__ bz)
{
    int idx = blockIdx.x * blockDim.x + threadIdx.x;
    if (idx >= B_SZ * LSEQ * D_INNER) return;
    int c = idx % D_INNER;
    int l = (idx / D_INNER) % LSEQ;
    int b = idx / (D_INNER * LSEQ);

    bool isx = (c < D_HALF);
    int ch = isx ? c : c - D_HALF;
    const float* w = isx ? wx : wz;
    float acc = isx ? bx[ch] : bz[ch];

#pragma unroll
    for (int j = 0; j < 4; j++) {
        int ll = l + j - 1;
        if (ll >= 0 && ll < LSEQ)
            acc = fmaf(w[j * D_HALF + ch],
                       g_xz[((size_t)(b * LSEQ + ll)) * D_INNER + c], acc);
    }
    float s = acc / (1.f + __expf(-acc));   /* SiLU */

    size_t row = (size_t)(b * LSEQ + l);
    if (isx) g_u[row * D_HALF + ch] = s;
    else     g_cat[row * D_INNER + D_HALF + ch] = s;
}

/* ------------------------------------------------------------------ */
/* Selective scan. One thread per (b, d). A[d][n] = -(n+1), so          */
/* dA_n = e^(n+1) with e = exp(-delta): ONE exp per step, powers by a   */
/* log-depth product tree. B,C (x_dbl cols 64..95, contiguous) staged   */
/* in smem in 64-step tiles. Writes y into left half of g_cat.          */
/* ------------------------------------------------------------------ */
#define SCAN_T 64
__global__ __launch_bounds__(128)
void scan_kernel(const float* __restrict__ Dvec)
{
    int b = blockIdx.y;
    int d = blockIdx.x * blockDim.x + threadIdx.x;

    __shared__ float sBC[SCAN_T][32];   /* [step][0..15 = B, 16..31 = C] */

    float h[D_STATE];
#pragma unroll
    for (int n = 0; n < D_STATE; n++) h[n] = 0.f;

    const float Dd = Dvec[d];
    const float* up = g_u     + (size_t)b * LSEQ * D_HALF + d;
    const float* dp = g_delta + (size_t)b * LSEQ * D_HALF + d;
    const float* xp = g_xdbl  + (size_t)b * LSEQ * XDBL_W + DT_RANK;
    float*       yp = g_cat   + (size_t)b * LSEQ * D_INNER + d;

    for (int l0 = 0; l0 < LSEQ; l0 += SCAN_T) {
        __syncthreads();
        for (int i = threadIdx.x; i < SCAN_T * 32; i += blockDim.x)
            sBC[i >> 5][i & 31] = xp[(size_t)(l0 + (i >> 5)) * XDBL_W + (i & 31)];
        __syncthreads();

#pragma unroll 4
        for (int t = 0; t < SCAN_T; t++) {
            int l = l0 + t;
            float del = dp[(size_t)l * D_HALF];
            float uu  = up[(size_t)l * D_HALF];
            float e   = __expf(-del);
            float du  = del * uu;

            /* pw[n] = e^(n+1), log-depth tree */
            float pw[D_STATE];
            pw[0] = e;
#pragma unroll
            for (int n = 1; n < D_STATE; n++)
                pw[n] = pw[n >> 1] * pw[(n - 1) >> 1];

            float y = 0.f;
#pragma unroll
            for (int n = 0; n < D_STATE; n++) {
                h[n] = fmaf(h[n], pw[n], du * sBC[t][n]);
                y    = fmaf(h[n], sBC[t][16 + n], y);
            }
            yp[(size_t)l * D_INNER] = fmaf(uu, Dd, y);
        }
    }
}

/* ------------------------------------------------------------------ */
extern "C" void kernel_launch(void* const* d_in, const int* in_sizes, int n_in,
                              void* d_out, int out_size)
{
    const float* x        = (const float*)d_in[0];
    const float* W_in     = (const float*)d_in[1];
    const float* conv_x_w = (const float*)d_in[2];
    const float* conv_x_b = (const float*)d_in[3];
    const float* conv_z_w = (const float*)d_in[4];
    const float* conv_z_b = (const float*)d_in[5];
    const float* W_xdbl   = (const float*)d_in[6];
    const float* W_dt     = (const float*)d_in[7];
    const float* inv_dt   = (const float*)d_in[8];
    const float* Dvec     = (const float*)d_in[9];
    const float* W_out    = (const float*)d_in[10];
    const float* b_out    = (const float*)d_in[11];
    float* out = (float*)d_out;

    float *xz, *u, *xdbl, *delta, *cat;
    cudaGetSymbolAddress((void**)&xz,    g_xz);
    cudaGetSymbolAddress((void**)&u,     g_u);
    cudaGetSymbolAddress((void**)&xdbl,  g_xdbl);
    cudaGetSymbolAddress((void**)&delta, g_delta);
    cudaGetSymbolAddress((void**)&cat,   g_cat);

    /* 1. xz = x @ W_in : (8192,1024)@(1024,2048) */
    sgemm_kernel<<<dim3(D_INNER / 128, ROWS / 128), 256>>>(
        x, W_in, xz, ROWS, D_INNER, D_MODEL,
        D_MODEL, D_INNER, D_INNER, 0, nullptr);

    /* 2. depthwise conv + SiLU on both halves */
    conv_silu_kernel<<<(B_SZ * LSEQ * D_INNER) / 256, 256>>>(
        conv_x_w, conv_x_b, conv_z_w, conv_z_b);

    /* 3. x_dbl = u @ W_xdbl : (8192,1024)@(1024,96) */
    sgemm_kernel<<<dim3(1, ROWS / 128), 256>>>(
        u, W_xdbl, xdbl, ROWS, XDBL_W, D_HALF,
        D_HALF, XDBL_W, XDBL_W, 0, nullptr);

    /* 4. delta = softplus(dt_low @ W_dt + 2*inv_dt) : (8192,64)@(64,1024) */
    sgemm_kernel<<<dim3(D_HALF / 128, ROWS / 128), 256>>>(
        xdbl, W_dt, delta, ROWS, D_HALF, DT_RANK,
        XDBL_W, D_HALF, D_HALF, 1, inv_dt);

    /* 5. selective scan -> y (left half of g_cat) */
    scan_kernel<<<dim3(D_HALF / 128, B_SZ), 128>>>(Dvec);

    /* 6. out = [y | z] @ W_out + b_out : (8192,2048)@(2048,1024) */
    sgemm_kernel<<<dim3(D_MODEL / 128, ROWS / 128), 256>>>(
        cat, W_out, out, ROWS, D_MODEL, D_INNER,
        D_INNER, D_MODEL, D_MODEL, 2, b_out);
}

// round 3
// speedup vs baseline: 1.6213x; 1.6213x over previous
#include <cuda_runtime.h>
#include <math.h>
#include <stdint.h>

#define B_SZ    4
#define LSEQ    2048
#define D_MODEL 1024
#define D_INNER 2048
#define D_HALF  1024
#define D_STATE 16
#define DT_RANK 64
#define ROWS    (B_SZ * LSEQ)   /* 8192 */
#define XDBL_W  96              /* DT_RANK + 2*D_STATE */

/* ------------------------------------------------------------------ */
/* Scratch (allocation-free rule: __device__ globals)                  */
/* ------------------------------------------------------------------ */
__device__ float g_xz   [ROWS * D_INNER];   /* 64 MB */
__device__ float g_u    [ROWS * D_HALF];    /* 32 MB  xs after conv+silu */
__device__ float g_xdbl [ROWS * XDBL_W];    /*  3 MB  [dt_low | B | C]   */
__device__ float g_delta[ROWS * D_HALF];    /* 32 MB */
__device__ float g_cat  [ROWS * D_INNER];   /* 64 MB  [y | z]            */

/* ------------------------------------------------------------------ */
/* TF32 tensor-core GEMM: C = A(MxK) @ B(KxN), row-major, strided.     */
/* mode 0: plain; mode 1: softplus(v + 2*bias[col]); mode 2: v+bias.   */
/* Req: M%128==0, K%16==0, N%4==0, lda/ldb multiples of 4.             */
/* CTA tile 128x128x16, 8 warps, warp tile 32x64, mma.m16n8k8.tf32.    */
/* ------------------------------------------------------------------ */
#define BM 128
#define BN 128
#define BK 16
#define SA 20    /* As row stride (floats): 8 rows hit 8 distinct banks */
#define SB 136   /* Bs row stride (floats): 544B, 16B-aligned rows      */

__device__ __forceinline__ uint32_t f2tf(float x) {
    uint32_t r;
    asm("cvt.rna.tf32.f32 %0, %1;" : "=r"(r) : "f"(x));
    return r;
}

__device__ __forceinline__ void mma_tf32(float* c, const uint32_t* a, const uint32_t* b) {
    asm volatile(
        "mma.sync.aligned.m16n8k8.row.col.f32.tf32.tf32.f32 "
        "{%0,%1,%2,%3}, {%4,%5,%6,%7}, {%8,%9}, {%0,%1,%2,%3};"
        : "+f"(c[0]), "+f"(c[1]), "+f"(c[2]), "+f"(c[3])
        : "r"(a[0]), "r"(a[1]), "r"(a[2]), "r"(a[3]), "r"(b[0]), "r"(b[1]));
}

__global__ __launch_bounds__(256)
void tgemm_kernel(const float* __restrict__ A, const float* __restrict__ B,
                  float* __restrict__ C, int M, int N, int K,
                  int lda, int ldb, int ldc,
                  int mode, const float* __restrict__ bias)
{
    __shared__ uint32_t As[BM * SA];
    __shared__ uint32_t Bs[BK * SB];

    const int tid    = threadIdx.x;
    const int lane   = tid & 31;
    const int wid    = tid >> 5;
    const int warp_m = wid & 3;          /* 0..3 -> 32-row strip  */
    const int warp_n = wid >> 2;         /* 0..1 -> 64-col strip  */
    const int block_row = blockIdx.y * BM;
    const int block_col = blockIdx.x * BN;

    float acc[2][8][4];
#pragma unroll
    for (int mt = 0; mt < 2; mt++)
#pragma unroll
        for (int nt = 0; nt < 8; nt++)
#pragma unroll
            for (int i = 0; i < 4; i++) acc[mt][nt][i] = 0.f;

    const int a_r = tid >> 2;            /* 0..63          */
    const int a_k = (tid & 3) << 2;      /* 0,4,8,12       */
    const int b_r = tid >> 5;            /* 0..7           */
    const int b_c = (tid & 31) << 2;     /* 0..124         */

    for (int k0 = 0; k0 < K; k0 += BK) {
        /* stage A (convert to tf32) */
#pragma unroll
        for (int i = 0; i < 2; i++) {
            int r = a_r + i * 64;
            float4 v = *reinterpret_cast<const float4*>(
                &A[(size_t)(block_row + r) * lda + k0 + a_k]);
            As[r * SA + a_k + 0] = f2tf(v.x);
            As[r * SA + a_k + 1] = f2tf(v.y);
            As[r * SA + a_k + 2] = f2tf(v.z);
            As[r * SA + a_k + 3] = f2tf(v.w);
        }
        /* stage B (convert to tf32) */
#pragma unroll
        for (int i = 0; i < 2; i++) {
            int r = b_r + i * 8;
            int col = block_col + b_c;
            float4 v = make_float4(0.f, 0.f, 0.f, 0.f);
            if (col < N)
                v = *reinterpret_cast<const float4*>(&B[(size_t)(k0 + r) * ldb + col]);
            uint4 t;
            t.x = f2tf(v.x); t.y = f2tf(v.y); t.z = f2tf(v.z); t.w = f2tf(v.w);
            *reinterpret_cast<uint4*>(&Bs[r * SB + b_c]) = t;
        }
        __syncthreads();

#pragma unroll
        for (int ks = 0; ks < 2; ks++) {
            uint32_t af[2][4];
            uint32_t bf[8][2];
            const int row0 = warp_m * 32 + (lane >> 2);
            const int kk   = ks * 8 + (lane & 3);
#pragma unroll
            for (int mt = 0; mt < 2; mt++) {
                int r = row0 + mt * 16;
                af[mt][0] = As[r * SA + kk];
                af[mt][1] = As[(r + 8) * SA + kk];
                af[mt][2] = As[r * SA + kk + 4];
                af[mt][3] = As[(r + 8) * SA + kk + 4];
            }
            const int coln = warp_n * 64 + (lane >> 2);
#pragma unroll
            for (int nt = 0; nt < 8; nt++) {
                bf[nt][0] = Bs[(ks * 8 + (lane & 3)) * SB + coln + nt * 8];
                bf[nt][1] = Bs[(ks * 8 + 4 + (lane & 3)) * SB + coln + nt * 8];
            }
#pragma unroll
            for (int mt = 0; mt < 2; mt++)
#pragma unroll
                for (int nt = 0; nt < 8; nt++)
                    mma_tf32(acc[mt][nt], af[mt], bf[nt]);
        }
        __syncthreads();
    }

    /* epilogue: c0,c1 at (row, col..col+1); c2,c3 at (row+8, ...) */
#pragma unroll
    for (int mt = 0; mt < 2; mt++) {
        int row = block_row + warp_m * 32 + mt * 16 + (lane >> 2);
#pragma unroll
        for (int nt = 0; nt < 8; nt++) {
            int col = block_col + warp_n * 64 + nt * 8 + (lane & 3) * 2;
            if (col < N) {
#pragma unroll
                for (int half = 0; half < 2; half++) {
                    int r = row + half * 8;
                    float v0 = acc[mt][nt][half * 2 + 0];
                    float v1 = acc[mt][nt][half * 2 + 1];
                    if (mode == 1) {
                        v0 += 2.f * bias[col];
                        v1 += 2.f * bias[col + 1];
                        v0 = (v0 > 20.f) ? v0 : log1pf(__expf(v0));
                        v1 = (v1 > 20.f) ? v1 : log1pf(__expf(v1));
                    } else if (mode == 2) {
                        v0 += bias[col];
                        v1 += bias[col + 1];
                    }
                    *reinterpret_cast<float2*>(&C[(size_t)r * ldc + col]) =
                        make_float2(v0, v1);
                }
            }
        }
    }
}

/* ------------------------------------------------------------------ */
/* Depthwise conv1d (k=4, SAME: pad_lo=1, pad_hi=2) + SiLU on both     */
/* halves of xz. xs -> g_u, z -> right half of g_cat.                  */
/* ------------------------------------------------------------------ */
__global__ __launch_bounds__(256)
void conv_silu_kernel(const float* __restrict__ wx, const float* __restrict__ bx,
                      const float* __restrict__ wz, const float* __restrict__ bz)
{
    int idx = blockIdx.x * blockDim.x + threadIdx.x;
    if (idx >= B_SZ * LSEQ * D_INNER) return;
    int c = idx % D_INNER;
    int l = (idx / D_INNER) % LSEQ;
    int b = idx / (D_INNER * LSEQ);

    bool isx = (c < D_HALF);
    int ch = isx ? c : c - D_HALF;
    const float* w = isx ? wx : wz;
    float acc = isx ? bx[ch] : bz[ch];

#pragma unroll
    for (int j = 0; j < 4; j++) {
        int ll = l + j - 1;
        if (ll >= 0 && ll < LSEQ)
            acc = fmaf(w[j * D_HALF + ch],
                       g_xz[((size_t)(b * LSEQ + ll)) * D_INNER + c], acc);
    }
    float s = acc / (1.f + __expf(-acc));   /* SiLU */

    size_t row = (size_t)(b * LSEQ + l);
    if (isx) g_u[row * D_HALF + ch] = s;
    else     g_cat[row * D_INNER + D_HALF + ch] = s;
}

/* ------------------------------------------------------------------ */
/* Selective scan. One thread per (b, d). A[d][n] = -(n+1), so          */
/* dA_n = e^(n+1) with e = exp(-delta): ONE exp per step, powers by a   */
/* log-depth product tree. B,C (x_dbl cols 64..95, contiguous) staged   */
/* in smem in 64-step tiles. Writes y into left half of g_cat.          */
/* ------------------------------------------------------------------ */
#define SCAN_T 64
__global__ __launch_bounds__(128)
void scan_kernel(const float* __restrict__ Dvec)
{
    int b = blockIdx.y;
    int d = blockIdx.x * blockDim.x + threadIdx.x;

    __shared__ float sBC[SCAN_T][32];   /* [step][0..15 = B, 16..31 = C] */

    float h[D_STATE];
#pragma unroll
    for (int n = 0; n < D_STATE; n++) h[n] = 0.f;

    const float Dd = Dvec[d];
    const float* up = g_u     + (size_t)b * LSEQ * D_HALF + d;
    const float* dp = g_delta + (size_t)b * LSEQ * D_HALF + d;
    const float* xp = g_xdbl  + (size_t)b * LSEQ * XDBL_W + DT_RANK;
    float*       yp = g_cat   + (size_t)b * LSEQ * D_INNER + d;

    for (int l0 = 0; l0 < LSEQ; l0 += SCAN_T) {
        __syncthreads();
        for (int i = threadIdx.x; i < SCAN_T * 32; i += blockDim.x)
            sBC[i >> 5][i & 31] = xp[(size_t)(l0 + (i >> 5)) * XDBL_W + (i & 31)];
        __syncthreads();

#pragma unroll 4
        for (int t = 0; t < SCAN_T; t++) {
            int l = l0 + t;
            float del = dp[(size_t)l * D_HALF];
            float uu  = up[(size_t)l * D_HALF];
            float e   = __expf(-del);
            float du  = del * uu;

            /* pw[n] = e^(n+1), log-depth tree */
            float pw[D_STATE];
            pw[0] = e;
#pragma unroll
            for (int n = 1; n < D_STATE; n++)
                pw[n] = pw[n >> 1] * pw[(n - 1) >> 1];

            float y = 0.f;
#pragma unroll
            for (int n = 0; n < D_STATE; n++) {
                h[n] = fmaf(h[n], pw[n], du * sBC[t][n]);
                y    = fmaf(h[n], sBC[t][16 + n], y);
            }
            yp[(size_t)l * D_INNER] = fmaf(uu, Dd, y);
        }
    }
}

/* ------------------------------------------------------------------ */
extern "C" void kernel_launch(void* const* d_in, const int* in_sizes, int n_in,
                              void* d_out, int out_size)
{
    const float* x        = (const float*)d_in[0];
    const float* W_in     = (const float*)d_in[1];
    const float* conv_x_w = (const float*)d_in[2];
    const float* conv_x_b = (const float*)d_in[3];
    const float* conv_z_w = (const float*)d_in[4];
    const float* conv_z_b = (const float*)d_in[5];
    const float* W_xdbl   = (const float*)d_in[6];
    const float* W_dt     = (const float*)d_in[7];
    const float* inv_dt   = (const float*)d_in[8];
    const float* Dvec     = (const float*)d_in[9];
    const float* W_out    = (const float*)d_in[10];
    const float* b_out    = (const float*)d_in[11];
    float* out = (float*)d_out;

    float *xz, *u, *xdbl, *delta, *cat;
    cudaGetSymbolAddress((void**)&xz,    g_xz);
    cudaGetSymbolAddress((void**)&u,     g_u);
    cudaGetSymbolAddress((void**)&xdbl,  g_xdbl);
    cudaGetSymbolAddress((void**)&delta, g_delta);
    cudaGetSymbolAddress((void**)&cat,   g_cat);

    /* 1. xz = x @ W_in : (8192,1024)@(1024,2048) */
    tgemm_kernel<<<dim3(D_INNER / BN, ROWS / BM), 256>>>(
        x, W_in, xz, ROWS, D_INNER, D_MODEL,
        D_MODEL, D_INNER, D_INNER, 0, nullptr);

    /* 2. depthwise conv + SiLU on both halves */
    conv_silu_kernel<<<(B_SZ * LSEQ * D_INNER) / 256, 256>>>(
        conv_x_w, conv_x_b, conv_z_w, conv_z_b);

    /* 3. x_dbl = u @ W_xdbl : (8192,1024)@(1024,96) */
    tgemm_kernel<<<dim3(1, ROWS / BM), 256>>>(
        u, W_xdbl, xdbl, ROWS, XDBL_W, D_HALF,
        D_HALF, XDBL_W, XDBL_W, 0, nullptr);

    /* 4. delta = softplus(dt_low @ W_dt + 2*inv_dt) : (8192,64)@(64,1024) */
    tgemm_kernel<<<dim3(D_HALF / BN, ROWS / BM), 256>>>(
        xdbl, W_dt, delta, ROWS, D_HALF, DT_RANK,
        XDBL_W, D_HALF, D_HALF, 1, inv_dt);

    /* 5. selective scan -> y (left half of g_cat) */
    scan_kernel<<<dim3(D_HALF / 128, B_SZ), 128>>>(Dvec);

    /* 6. out = [y | z] @ W_out + b_out : (8192,2048)@(2048,1024) */
    tgemm_kernel<<<dim3(D_MODEL / BN, ROWS / BM), 256>>>(
        cat, W_out, out, ROWS, D_MODEL, D_INNER,
        D_INNER, D_MODEL, D_MODEL, 2, b_out);
}